// round 15
// baseline (speedup 1.0000x reference)
#include <cuda_runtime.h>
#include <cuda_fp16.h>
#include <cstdint>

#define KCAP 512
#define DDIM 1024
#define BMAX 16384
#define PAD  520

// ---------------- device scratch (no allocations allowed) ----------------
__device__ __align__(16) float g_At[KCAP * KCAP];   // fp32 0.1*A_diff^T (for k_prep)
// Lane-major f16 At for k_main B fragments (see R11/R12)
__device__ __align__(16) unsigned g_AtB[32 * 16 * 2 * 32 * 4];
// x as mma A-fragments: [(rt*64+gg)*32+lane] uint4 {a0,a1,a2,a3}  (f16x2 k-pairs)
__device__ uint4 g_xB[1024 * 64 * 32];
// W as mma B-fragments: [(ctp*64+gg)*32+lane] uint4 {b0_e, b1_e, b0_o, b1_o}
__device__ uint4 g_wB[32 * 64 * 32];
__device__ __align__(16) float g_u1[KCAP];
__device__ __align__(16) float g_w1[KCAP];
__device__ float g_sc[2];                            // {1/T_eff, c}

// ---------------- helpers ----------------
__device__ __forceinline__ float blkMax256(float v, float* sc) {
    #pragma unroll
    for (int o = 16; o > 0; o >>= 1) v = fmaxf(v, __shfl_xor_sync(0xffffffffu, v, o));
    if ((threadIdx.x & 31) == 0) sc[threadIdx.x >> 5] = v;
    __syncthreads();
    float r = sc[0];
    #pragma unroll
    for (int i = 1; i < 8; i++) r = fmaxf(r, sc[i]);
    __syncthreads();
    return r;
}
__device__ __forceinline__ float blkSum256(float v, float* sc) {
    #pragma unroll
    for (int o = 16; o > 0; o >>= 1) v += __shfl_xor_sync(0xffffffffu, v, o);
    if ((threadIdx.x & 31) == 0) sc[threadIdx.x >> 5] = v;
    __syncthreads();
    float r = sc[0];
    #pragma unroll
    for (int i = 1; i < 8; i++) r += sc[i];
    __syncthreads();
    return r;
}
__device__ __forceinline__ unsigned packhf(float lo, float hi) {
    unsigned r;
    asm("cvt.rn.f16x2.f32 %0, %1, %2;" : "=r"(r) : "f"(hi), "f"(lo));
    return r;
}

#define MMA_F16(c, a0, a1, a2, a3, b0, b1)                                             \
    asm volatile(                                                                       \
        "mma.sync.aligned.m16n8k16.row.col.f32.f16.f16.f32 "                            \
        "{%0,%1,%2,%3},{%4,%5,%6,%7},{%8,%9},{%0,%1,%2,%3};"                            \
        : "+f"((c)[0]), "+f"((c)[1]), "+f"((c)[2]), "+f"((c)[3])                        \
        : "r"(a0), "r"(a1), "r"(a2), "r"(a3), "r"(b0), "r"(b1))

// ---------------- P0: scalars ----------------
__global__ void k_scalars(const float* __restrict__ lT, const float* __restrict__ lc,
                          const void* __restrict__ tp) {
    if (threadIdx.x == 0) {
        unsigned w = *(const unsigned*)tp;
        float ft = __uint_as_float(w);
        float tempv = (fabsf(ft) > 1e-30f && fabsf(ft) < 1e30f) ? ft : (float)(int)w;
        float T = fminf(fmaxf(expf(lT[0]) * tempv, 0.05f), 10.0f);
        g_sc[0] = 1.0f / T;
        g_sc[1] = fminf(fmaxf(expf(lc[0]), 0.01f), 10.0f);
    }
}

// ---------------- P1: symmetric softmax -> At fp32 + lane-major f16 ----------------
__global__ void __launch_bounds__(256) k_adiff(const float* __restrict__ A) {
    __shared__ float scr[8];
    __shared__ float col[KCAP];
    const int j = blockIdx.x, tid = threadIdx.x;
    float v0 = 0.5f * (A[j * KCAP + tid]       + A[tid * KCAP + j]);
    float v1 = 0.5f * (A[j * KCAP + tid + 256] + A[(tid + 256) * KCAP + j]);
    float M = blkMax256(fmaxf(v0, v1), scr);
    float e0 = __expf(v0 - M), e1 = __expf(v1 - M);
    float S = blkSum256(e0 + e1, scr);
    float r = 0.1f / S;
    float a0 = e0 * r, a1 = e1 * r;
    g_At[tid * KCAP + j]         = a0;
    g_At[(tid + 256) * KCAP + j] = a1;
    col[tid] = a0; col[tid + 256] = a1;
    __syncthreads();
    if (tid < 128) {
        int gg = tid >> 2, kq = tid & 3;
        int p0 = gg * 8 + kq;
        int p1 = p0 + 4;
        uint2 v;
        v.x = packhf(col[2 * p0], col[2 * p0 + 1]);
        v.y = packhf(col[2 * p1], col[2 * p1 + 1]);
        int w = j >> 5, t = (j >> 3) & 3, jj = t >> 1, tpar = t & 1, nq = j & 7;
        int lane = nq * 4 + kq;
        unsigned base = (unsigned)((((gg * 16 + w) * 2 + jj) * 32 + lane) * 4 + tpar * 2);
        g_AtB[base]     = v.x;
        g_AtB[base + 1] = v.y;
    }
}

// ---------------- P2: fold iteration 0 (16 blocks x 8-way k-split) ----------------
__global__ void __launch_bounds__(256) k_prep(const float* __restrict__ brun) {
    __shared__ float br[KCAP];
    __shared__ float sg[KCAP];
    __shared__ float scr[8];
    __shared__ float redu[256];
    __shared__ float redw[256];
    const int tid = threadIdx.x;
    const float invT = g_sc[0];
    float v0 = brun[tid], v1 = brun[tid + 256];
    br[tid] = v0; br[tid + 256] = v1;
    float M = blkMax256(fmaxf(v0, v1), scr);
    float e0 = __expf((v0 - M) * invT), e1 = __expf((v1 - M) * invT);
    float S = blkSum256(e0 + e1, scr);
    float is = 1.0f / S;
    sg[tid] = e0 * is; sg[tid + 256] = e1 * is;
    __syncthreads();
    const int j = blockIdx.x * 32 + (tid & 31);
    const int ks = tid >> 5;
    float u = 0.0f, w = 0.0f;
    #pragma unroll 8
    for (int k = ks * 64; k < ks * 64 + 64; k++) {
        float at = g_At[k * KCAP + j];
        u = fmaf(br[k], at, u);
        w = fmaf(sg[k], at, w);
    }
    redu[tid] = u; redw[tid] = w;
    __syncthreads();
    if (tid < 32) {
        float uu = 0.0f, ww = 0.0f;
        #pragma unroll
        for (int s2 = 0; s2 < 8; s2++) { uu += redu[tid + 32 * s2]; ww += redw[tid + 32 * s2]; }
        int jj = blockIdx.x * 32 + tid;
        g_u1[jj] = br[jj] + uu;
        g_w1[jj] = sg[jj] + ww;
    }
}

// ---------------- P3a: x -> A-fragment layout (direct gmem) ----------------
__global__ void __launch_bounds__(256) k_convx(const float* __restrict__ x) {
    const int rt = blockIdx.x;
    const int w = threadIdx.x >> 5, lane = threadIdx.x & 31;
    const float* xr0 = x + ((size_t)rt * 16 + (lane >> 2)) * DDIM;
    const float* xr1 = xr0 + 8 * DDIM;
    #pragma unroll
    for (int i = 0; i < 8; i++) {
        int gg = i * 8 + w;
        int k0 = gg * 16 + 2 * (lane & 3);
        float2 a = *(const float2*)(xr0 + k0);
        float2 b = *(const float2*)(xr1 + k0);
        float2 c = *(const float2*)(xr0 + k0 + 8);
        float2 d = *(const float2*)(xr1 + k0 + 8);
        uint4 v;
        v.x = packhf(a.x, a.y);
        v.y = packhf(b.x, b.y);
        v.z = packhf(c.x, c.y);
        v.w = packhf(d.x, d.y);
        g_xB[(size_t)(rt * 64 + gg) * 32 + lane] = v;
    }
}

// ---------------- P3b: W -> B-fragment layout (direct gmem) ----------------
__global__ void __launch_bounds__(256) k_convw(const float* __restrict__ W) {
    const int ctp = blockIdx.x;
    const int w = threadIdx.x >> 5, lane = threadIdx.x & 31;
    const float* wr0 = W + ((size_t)ctp * 16 + (lane >> 2)) * DDIM;
    const float* wr1 = wr0 + 8 * DDIM;
    #pragma unroll
    for (int i = 0; i < 8; i++) {
        int gg = i * 8 + w;
        int k0 = gg * 16 + 2 * (lane & 3);
        float2 a = *(const float2*)(wr0 + k0);
        float2 b = *(const float2*)(wr0 + k0 + 8);
        float2 c = *(const float2*)(wr1 + k0);
        float2 d = *(const float2*)(wr1 + k0 + 8);
        uint4 v;
        v.x = packhf(a.x, a.y);
        v.y = packhf(b.x, b.y);
        v.z = packhf(c.x, c.y);
        v.w = packhf(d.x, d.y);
        g_wB[(size_t)(ctp * 64 + gg) * 32 + lane] = v;
    }
}

// ---------------- MAIN (merged): norm GEMM + agreement + 4 routing iters + theta ----------------
// smem: b_s[64][520] f32 | bh[64][260] u32 | agrs[64] | red[64*4]
#define BHS 260
#define SMEM_MAIN_BYTES ((64 * PAD + 64 + 256) * 4 + 64 * BHS * 4)

__global__ void __launch_bounds__(512, 1) k_main(float* __restrict__ out) {
    extern __shared__ float sm[];
    float*    b_s  = sm;                              // [64][PAD]
    unsigned* bh   = (unsigned*)(sm + 64 * PAD);      // [64][BHS]
    float*    agrs = (float*)(bh + 64 * BHS);         // [64]
    float*    red  = agrs + 64;                       // [64][4]

    const int tid  = threadIdx.x;
    const int lane = tid & 31;
    const int wrp  = tid >> 5;
    const int row0 = blockIdx.x * 64;
    const float invT = g_sc[0];

    const int r  = tid >> 3;
    const int t8 = tid & 7;
    float* base = b_s + r * PAD + t8 * 4;
    unsigned* bhrow = bh + r * BHS + t8 * 2;

    // ======== PHASE 1: norm GEMM (u = x@W.T for this block's 64 rows, all 512 caps) ========
    {
        const int rw = wrp & 3;        // 16-row group (rt = blockIdx.x*4 + rw)
        const int cs = wrp >> 2;       // 128-col stripe (ctp = cs*8 .. cs*8+7)
        const uint4* xb = g_xB + ((size_t)(blockIdx.x * 4 + rw) * 64) * 32 + lane;
        const uint4* wb = g_wB + ((size_t)(cs * 8) * 64) * 32 + lane;

        float acc[16][4];
        #pragma unroll
        for (int nt = 0; nt < 16; nt++)
            #pragma unroll
            for (int q = 0; q < 4; q++) acc[nt][q] = 0.0f;

        uint4 A = xb[0];
        uint4 Bv[8];
        #pragma unroll
        for (int p = 0; p < 8; p++) Bv[p] = wb[p * 2048];

        #pragma unroll 2
        for (int gg = 0; gg < 64; gg++) {
            uint4 A2;
            uint4 B2[8];
            if (gg < 63) {
                A2 = xb[(gg + 1) * 32];
                const uint4* wn = wb + (gg + 1) * 32;
                #pragma unroll
                for (int p = 0; p < 8; p++) B2[p] = wn[p * 2048];
            }
            #pragma unroll
            for (int p = 0; p < 8; p++) {
                MMA_F16(acc[2 * p],     A.x, A.y, A.z, A.w, Bv[p].x, Bv[p].y);
                MMA_F16(acc[2 * p + 1], A.x, A.y, A.z, A.w, Bv[p].z, Bv[p].w);
            }
            A = A2;
            #pragma unroll
            for (int p = 0; p < 8; p++) Bv[p] = B2[p];
        }

        // per-row sum of squares over this warp's 128 cols
        #pragma unroll
        for (int h = 0; h < 2; h++) {
            float s = 0.0f;
            #pragma unroll
            for (int nt = 0; nt < 16; nt++) {
                float a = acc[nt][2 * h], b = acc[nt][2 * h + 1];
                s = fmaf(a, a, fmaf(b, b, s));
            }
            s += __shfl_xor_sync(0xffffffffu, s, 1);
            s += __shfl_xor_sync(0xffffffffu, s, 2);
            if ((lane & 3) == 0) {
                int rloc = rw * 16 + (lane >> 2) + h * 8;
                red[rloc * 4 + cs] = s;
            }
        }
    }
    __syncthreads();

    // ======== agreement (per row, in-block) ========
    if (tid < 64) {
        float ns = red[tid * 4] + red[tid * 4 + 1] + red[tid * 4 + 2] + red[tid * 4 + 3];
        ns = fmaxf(ns, 1e-10f);
        float c = g_sc[1];
        float sc2 = c * ns / (1.0f + c * ns);
        agrs[tid] = sc2 * sqrtf(ns);
    }
    __syncthreads();

    // ======== init b = u1 + a*w1 ========
    {
        float uj = g_u1[tid & 511];
        float wj = g_w1[tid & 511];
        #pragma unroll 8
        for (int r2 = 0; r2 < 64; r2++)
            b_s[r2 * PAD + tid] = fmaf(agrs[r2], wj, uj);
    }
    __syncthreads();

    // ======== 4 routing iterations ========
    const uint4* bbase = (const uint4*)g_AtB + (wrp * 2) * 32 + lane;

    for (int it = 0; it < 4; it++) {
        // ---- b += a * softmax(b/T); shfl reductions over 8-lane row groups ----
        float mx = -3.4e38f;
        #pragma unroll
        for (int j = 0; j < 16; j++) {
            float4 v = *(const float4*)(base + j * 32);
            mx = fmaxf(mx, fmaxf(fmaxf(v.x, v.y), fmaxf(v.z, v.w)));
        }
        #pragma unroll
        for (int o = 4; o > 0; o >>= 1) mx = fmaxf(mx, __shfl_xor_sync(0xffffffffu, mx, o));
        float m = mx;
        float s = 0.0f;
        #pragma unroll
        for (int j = 0; j < 16; j++) {
            float4 v = *(const float4*)(base + j * 32);
            s += __expf((v.x - m) * invT) + __expf((v.y - m) * invT)
               + __expf((v.z - m) * invT) + __expf((v.w - m) * invT);
        }
        #pragma unroll
        for (int o = 4; o > 0; o >>= 1) s += __shfl_xor_sync(0xffffffffu, s, o);
        float aS = agrs[r] / s;
        #pragma unroll
        for (int j = 0; j < 16; j++) {
            float4 v = *(const float4*)(base + j * 32);
            v.x = fmaf(aS, __expf((v.x - m) * invT), v.x);
            v.y = fmaf(aS, __expf((v.y - m) * invT), v.y);
            v.z = fmaf(aS, __expf((v.z - m) * invT), v.z);
            v.w = fmaf(aS, __expf((v.w - m) * invT), v.w);
            *(float4*)(base + j * 32) = v;
            *(uint2*)(bhrow + j * 16) = make_uint2(packhf(v.x, v.y), packhf(v.z, v.w));
        }
        __syncthreads();   // bh ready for all warps

        // ---- d = b @ AtH: zero-barrier GEMM (B from L2 via LDG, A from bh) ----
        float acc[4][4][4];
        #pragma unroll
        for (int mt = 0; mt < 4; mt++)
            #pragma unroll
            for (int nt = 0; nt < 4; nt++)
                #pragma unroll
                for (int q = 0; q < 4; q++) acc[mt][nt][q] = 0.0f;

        uint4 B0 = bbase[0], B1 = bbase[32];
        #pragma unroll 4
        for (int gg = 0; gg < 32; gg++) {
            uint4 C0, C1;
            if (gg < 31) {
                const uint4* nb = bbase + (gg + 1) * 1024;
                C0 = nb[0]; C1 = nb[32];
            }
            const int kb = gg * 8 + (lane & 3);
            #pragma unroll
            for (int mt = 0; mt < 4; mt++) {
                int ra = (mt * 16 + (lane >> 2)) * BHS + kb;
                unsigned a0 = bh[ra];
                unsigned a1 = bh[ra + 8 * BHS];
                unsigned a2 = bh[ra + 4];
                unsigned a3 = bh[ra + 8 * BHS + 4];
                MMA_F16(acc[mt][0], a0, a1, a2, a3, B0.x, B0.y);
                MMA_F16(acc[mt][1], a0, a1, a2, a3, B0.z, B0.w);
                MMA_F16(acc[mt][2], a0, a1, a2, a3, B1.x, B1.y);
                MMA_F16(acc[mt][3], a0, a1, a2, a3, B1.z, B1.w);
            }
            B0 = C0; B1 = C1;
        }

        // ---- b += d ----
        #pragma unroll
        for (int mt = 0; mt < 4; mt++) {
            int row = mt * 16 + (lane >> 2);
            #pragma unroll
            for (int nt = 0; nt < 4; nt++) {
                int col = wrp * 32 + nt * 8 + 2 * (lane & 3);
                float* p = b_s + row * PAD + col;
                p[0]           += acc[mt][nt][0];
                p[1]           += acc[mt][nt][1];
                p[8 * PAD]     += acc[mt][nt][2];
                p[8 * PAD + 1] += acc[mt][nt][3];
            }
        }
        __syncthreads();
    }

    // ======== theta = softmax(b/T) -> out ========
    {
        float mx = -3.4e38f;
        #pragma unroll
        for (int j = 0; j < 16; j++) {
            float4 v = *(const float4*)(base + j * 32);
            mx = fmaxf(mx, fmaxf(fmaxf(v.x, v.y), fmaxf(v.z, v.w)));
        }
        #pragma unroll
        for (int o = 4; o > 0; o >>= 1) mx = fmaxf(mx, __shfl_xor_sync(0xffffffffu, mx, o));
        float m = mx;
        float s = 0.0f;
        #pragma unroll
        for (int j = 0; j < 16; j++) {
            float4 v = *(const float4*)(base + j * 32);
            s += __expf((v.x - m) * invT) + __expf((v.y - m) * invT)
               + __expf((v.z - m) * invT) + __expf((v.w - m) * invT);
        }
        #pragma unroll
        for (int o = 4; o > 0; o >>= 1) s += __shfl_xor_sync(0xffffffffu, s, o);
        float iS = 1.0f / s;
        float* op = out + (size_t)(row0 + r) * KCAP + t8 * 4;
        #pragma unroll
        for (int j = 0; j < 16; j++) {
            float4 v = *(const float4*)(base + j * 32);
            float4 o;
            o.x = __expf((v.x - m) * invT) * iS;
            o.y = __expf((v.y - m) * invT) * iS;
            o.z = __expf((v.z - m) * invT) * iS;
            o.w = __expf((v.w - m) * invT) * iS;
            *(float4*)(op + j * 32) = o;
        }
    }
}

// ---------------- launcher ----------------
extern "C" void kernel_launch(void* const* d_in, const int* in_sizes, int n_in,
                              void* d_out, int out_size) {
    const float* x    = (const float*)d_in[0];
    const float* W    = (const float*)d_in[1];
    const float* A    = (const float*)d_in[2];
    const float* lT   = (const float*)d_in[3];
    const float* lc   = (const float*)d_in[4];
    const float* brun = (const float*)d_in[5];
    const void*  temp = d_in[6];
    const int B = in_sizes[0] / DDIM;   // 16384

    cudaFuncSetAttribute(k_main, cudaFuncAttributeMaxDynamicSharedMemorySize,
                         SMEM_MAIN_BYTES);

    k_scalars<<<1, 32>>>(lT, lc, temp);
    k_adiff<<<KCAP, 256>>>(A);
    k_prep<<<16, 256>>>(brun);
    k_convx<<<B / 16, 256>>>(x);
    k_convw<<<KCAP / 16, 256>>>(W);
    k_main<<<B / 64, 512, SMEM_MAIN_BYTES>>>((float*)d_out);
}

// round 16
// speedup vs baseline: 1.2130x; 1.2130x over previous
#include <cuda_runtime.h>
#include <cuda_fp16.h>
#include <cstdint>

#define KCAP 512
#define DDIM 1024
#define BMAX 16384
#define PAD  520

// ---------------- device scratch (no allocations allowed) ----------------
__device__ __align__(16) float g_At[KCAP * KCAP];   // fp32 0.1*A_diff^T (for k_prep)
// Lane-major f16 At for k_main B fragments (see R11/R12)
__device__ __align__(16) unsigned g_AtB[32 * 16 * 2 * 32 * 4];
// x as mma A-fragments: [(rt*64+gg)*32+lane] uint4 {a0,a1,a2,a3}  (f16x2 k-pairs)
__device__ uint4 g_xB[1024 * 64 * 32];
// W as mma B-fragments: [(ctp*64+gg)*32+lane] uint4 {b0_e, b1_e, b0_o, b1_o}
__device__ uint4 g_wB[32 * 64 * 32];
__device__ __align__(16) float g_u1[KCAP];
__device__ __align__(16) float g_w1[KCAP];
__device__ float g_sc[2];                            // {1/T_eff, c}

// ---------------- helpers ----------------
__device__ __forceinline__ float blkMax256(float v, float* sc) {
    #pragma unroll
    for (int o = 16; o > 0; o >>= 1) v = fmaxf(v, __shfl_xor_sync(0xffffffffu, v, o));
    if ((threadIdx.x & 31) == 0) sc[threadIdx.x >> 5] = v;
    __syncthreads();
    float r = sc[0];
    #pragma unroll
    for (int i = 1; i < 8; i++) r = fmaxf(r, sc[i]);
    __syncthreads();
    return r;
}
__device__ __forceinline__ float blkSum256(float v, float* sc) {
    #pragma unroll
    for (int o = 16; o > 0; o >>= 1) v += __shfl_xor_sync(0xffffffffu, v, o);
    if ((threadIdx.x & 31) == 0) sc[threadIdx.x >> 5] = v;
    __syncthreads();
    float r = sc[0];
    #pragma unroll
    for (int i = 1; i < 8; i++) r += sc[i];
    __syncthreads();
    return r;
}
__device__ __forceinline__ unsigned packhf(float lo, float hi) {
    unsigned r;
    asm("cvt.rn.f16x2.f32 %0, %1, %2;" : "=r"(r) : "f"(hi), "f"(lo));
    return r;
}

#define MMA_F16(c, a0, a1, a2, a3, b0, b1)                                             \
    asm volatile(                                                                       \
        "mma.sync.aligned.m16n8k16.row.col.f32.f16.f16.f32 "                            \
        "{%0,%1,%2,%3},{%4,%5,%6,%7},{%8,%9},{%0,%1,%2,%3};"                            \
        : "+f"((c)[0]), "+f"((c)[1]), "+f"((c)[2]), "+f"((c)[3])                        \
        : "r"(a0), "r"(a1), "r"(a2), "r"(a3), "r"(b0), "r"(b1))

// ---------------- P0: scalars ----------------
__global__ void k_scalars(const float* __restrict__ lT, const float* __restrict__ lc,
                          const void* __restrict__ tp) {
    if (threadIdx.x == 0) {
        unsigned w = *(const unsigned*)tp;
        float ft = __uint_as_float(w);
        float tempv = (fabsf(ft) > 1e-30f && fabsf(ft) < 1e30f) ? ft : (float)(int)w;
        float T = fminf(fmaxf(expf(lT[0]) * tempv, 0.05f), 10.0f);
        g_sc[0] = 1.0f / T;
        g_sc[1] = fminf(fmaxf(expf(lc[0]), 0.01f), 10.0f);
    }
}

// ---------------- P1: symmetric softmax -> At fp32 + lane-major f16 ----------------
__global__ void __launch_bounds__(256) k_adiff(const float* __restrict__ A) {
    __shared__ float scr[8];
    __shared__ float col[KCAP];
    const int j = blockIdx.x, tid = threadIdx.x;
    float v0 = 0.5f * (A[j * KCAP + tid]       + A[tid * KCAP + j]);
    float v1 = 0.5f * (A[j * KCAP + tid + 256] + A[(tid + 256) * KCAP + j]);
    float M = blkMax256(fmaxf(v0, v1), scr);
    float e0 = __expf(v0 - M), e1 = __expf(v1 - M);
    float S = blkSum256(e0 + e1, scr);
    float r = 0.1f / S;
    float a0 = e0 * r, a1 = e1 * r;
    g_At[tid * KCAP + j]         = a0;
    g_At[(tid + 256) * KCAP + j] = a1;
    col[tid] = a0; col[tid + 256] = a1;
    __syncthreads();
    if (tid < 128) {
        int gg = tid >> 2, kq = tid & 3;
        int p0 = gg * 8 + kq;
        int p1 = p0 + 4;
        uint2 v;
        v.x = packhf(col[2 * p0], col[2 * p0 + 1]);
        v.y = packhf(col[2 * p1], col[2 * p1 + 1]);
        int w = j >> 5, t = (j >> 3) & 3, jj = t >> 1, tpar = t & 1, nq = j & 7;
        int lane = nq * 4 + kq;
        unsigned base = (unsigned)((((gg * 16 + w) * 2 + jj) * 32 + lane) * 4 + tpar * 2);
        g_AtB[base]     = v.x;
        g_AtB[base + 1] = v.y;
    }
}

// ---------------- P2: fold iteration 0 (16 blocks x 8-way k-split) ----------------
__global__ void __launch_bounds__(256) k_prep(const float* __restrict__ brun) {
    __shared__ float br[KCAP];
    __shared__ float sg[KCAP];
    __shared__ float scr[8];
    __shared__ float redu[256];
    __shared__ float redw[256];
    const int tid = threadIdx.x;
    const float invT = g_sc[0];
    float v0 = brun[tid], v1 = brun[tid + 256];
    br[tid] = v0; br[tid + 256] = v1;
    float M = blkMax256(fmaxf(v0, v1), scr);
    float e0 = __expf((v0 - M) * invT), e1 = __expf((v1 - M) * invT);
    float S = blkSum256(e0 + e1, scr);
    float is = 1.0f / S;
    sg[tid] = e0 * is; sg[tid + 256] = e1 * is;
    __syncthreads();
    const int j = blockIdx.x * 32 + (tid & 31);
    const int ks = tid >> 5;
    float u = 0.0f, w = 0.0f;
    #pragma unroll 8
    for (int k = ks * 64; k < ks * 64 + 64; k++) {
        float at = g_At[k * KCAP + j];
        u = fmaf(br[k], at, u);
        w = fmaf(sg[k], at, w);
    }
    redu[tid] = u; redw[tid] = w;
    __syncthreads();
    if (tid < 32) {
        float uu = 0.0f, ww = 0.0f;
        #pragma unroll
        for (int s2 = 0; s2 < 8; s2++) { uu += redu[tid + 32 * s2]; ww += redw[tid + 32 * s2]; }
        int jj = blockIdx.x * 32 + tid;
        g_u1[jj] = br[jj] + uu;
        g_w1[jj] = sg[jj] + ww;
    }
}

// ---------------- P3a: x -> A-fragment layout (direct gmem) ----------------
__global__ void __launch_bounds__(256) k_convx(const float* __restrict__ x) {
    const int rt = blockIdx.x;
    const int w = threadIdx.x >> 5, lane = threadIdx.x & 31;
    const float* xr0 = x + ((size_t)rt * 16 + (lane >> 2)) * DDIM;
    const float* xr1 = xr0 + 8 * DDIM;
    #pragma unroll
    for (int i = 0; i < 8; i++) {
        int gg = i * 8 + w;
        int k0 = gg * 16 + 2 * (lane & 3);
        float2 a = *(const float2*)(xr0 + k0);
        float2 b = *(const float2*)(xr1 + k0);
        float2 c = *(const float2*)(xr0 + k0 + 8);
        float2 d = *(const float2*)(xr1 + k0 + 8);
        uint4 v;
        v.x = packhf(a.x, a.y);
        v.y = packhf(b.x, b.y);
        v.z = packhf(c.x, c.y);
        v.w = packhf(d.x, d.y);
        g_xB[(size_t)(rt * 64 + gg) * 32 + lane] = v;
    }
}

// ---------------- P3b: W -> B-fragment layout (direct gmem) ----------------
__global__ void __launch_bounds__(256) k_convw(const float* __restrict__ W) {
    const int ctp = blockIdx.x;
    const int w = threadIdx.x >> 5, lane = threadIdx.x & 31;
    const float* wr0 = W + ((size_t)ctp * 16 + (lane >> 2)) * DDIM;
    const float* wr1 = wr0 + 8 * DDIM;
    #pragma unroll
    for (int i = 0; i < 8; i++) {
        int gg = i * 8 + w;
        int k0 = gg * 16 + 2 * (lane & 3);
        float2 a = *(const float2*)(wr0 + k0);
        float2 b = *(const float2*)(wr0 + k0 + 8);
        float2 c = *(const float2*)(wr1 + k0);
        float2 d = *(const float2*)(wr1 + k0 + 8);
        uint4 v;
        v.x = packhf(a.x, a.y);
        v.y = packhf(b.x, b.y);
        v.z = packhf(c.x, c.y);
        v.w = packhf(d.x, d.y);
        g_wB[(size_t)(ctp * 64 + gg) * 32 + lane] = v;
    }
}

// ---------------- MAIN (merged, spill-safe): norm GEMM + agreement + routing + theta ----------------
// Phase-1 warp tile = 32 rows x 64 cols (R14 k_norm shape): acc[2][8][4].
// smem: b_s[64][520] f32 | bh[64][260] u32 | agrs[64] | red[64*8]
#define BHS 260
#define SMEM_MAIN_BYTES ((64 * PAD + 64 + 512) * 4 + 64 * BHS * 4)

__global__ void __launch_bounds__(512, 1) k_main(float* __restrict__ out) {
    extern __shared__ float sm[];
    float*    b_s  = sm;                              // [64][PAD]
    unsigned* bh   = (unsigned*)(sm + 64 * PAD);      // [64][BHS]
    float*    agrs = (float*)(bh + 64 * BHS);         // [64]
    float*    red  = agrs + 64;                       // [64][8]

    const int tid  = threadIdx.x;
    const int lane = tid & 31;
    const int wrp  = tid >> 5;
    const int row0 = blockIdx.x * 64;
    const float invT = g_sc[0];

    const int r  = tid >> 3;
    const int t8 = tid & 7;
    float* base = b_s + r * PAD + t8 * 4;
    unsigned* bhrow = bh + r * BHS + t8 * 2;

    // ======== PHASE 1: norm GEMM, warp tile 32 rows x 64 cols ========
    {
        const int rw = wrp & 1;        // row group of 32 (2 rt tiles)
        const int cs = wrp >> 1;       // 0..7 col stripe of 64 (4 ctp tiles)
        const uint4* xb = g_xB + ((size_t)(blockIdx.x * 4 + rw * 2) * 64) * 32 + lane;
        const uint4* wb = g_wB + ((size_t)(cs * 4) * 64) * 32 + lane;

        float acc[2][8][4];
        #pragma unroll
        for (int mt = 0; mt < 2; mt++)
            #pragma unroll
            for (int nt = 0; nt < 8; nt++)
                #pragma unroll
                for (int q = 0; q < 4; q++) acc[mt][nt][q] = 0.0f;

        uint4 A[2], Bv[4];
        #pragma unroll
        for (int mt = 0; mt < 2; mt++) A[mt] = xb[mt * 2048];
        #pragma unroll
        for (int p = 0; p < 4; p++) Bv[p] = wb[p * 2048];

        #pragma unroll 4
        for (int gg = 0; gg < 64; gg++) {
            uint4 A2[2], B2[4];
            if (gg < 63) {
                const uint4* xn = xb + (gg + 1) * 32;
                const uint4* wn = wb + (gg + 1) * 32;
                #pragma unroll
                for (int mt = 0; mt < 2; mt++) A2[mt] = xn[mt * 2048];
                #pragma unroll
                for (int p = 0; p < 4; p++) B2[p] = wn[p * 2048];
            }
            #pragma unroll
            for (int mt = 0; mt < 2; mt++) {
                #pragma unroll
                for (int p = 0; p < 4; p++) {
                    MMA_F16(acc[mt][2 * p],     A[mt].x, A[mt].y, A[mt].z, A[mt].w, Bv[p].x, Bv[p].y);
                    MMA_F16(acc[mt][2 * p + 1], A[mt].x, A[mt].y, A[mt].z, A[mt].w, Bv[p].z, Bv[p].w);
                }
            }
            #pragma unroll
            for (int mt = 0; mt < 2; mt++) A[mt] = A2[mt];
            #pragma unroll
            for (int p = 0; p < 4; p++) Bv[p] = B2[p];
        }

        // per-row sum of squares over this warp's 64 cols
        #pragma unroll
        for (int mt = 0; mt < 2; mt++) {
            #pragma unroll
            for (int h = 0; h < 2; h++) {
                float s = 0.0f;
                #pragma unroll
                for (int nt = 0; nt < 8; nt++) {
                    float a = acc[mt][nt][2 * h], b = acc[mt][nt][2 * h + 1];
                    s = fmaf(a, a, fmaf(b, b, s));
                }
                s += __shfl_xor_sync(0xffffffffu, s, 1);
                s += __shfl_xor_sync(0xffffffffu, s, 2);
                if ((lane & 3) == 0) {
                    int rloc = rw * 32 + mt * 16 + (lane >> 2) + h * 8;
                    red[rloc * 8 + cs] = s;
                }
            }
        }
    }
    __syncthreads();

    // ======== agreement (in-block) ========
    if (tid < 64) {
        float ns = 0.0f;
        #pragma unroll
        for (int q = 0; q < 8; q++) ns += red[tid * 8 + q];
        ns = fmaxf(ns, 1e-10f);
        float c = g_sc[1];
        float sc2 = c * ns / (1.0f + c * ns);
        agrs[tid] = sc2 * sqrtf(ns);
    }
    __syncthreads();

    // ======== init b = u1 + a*w1 ========
    {
        float uj = g_u1[tid & 511];
        float wj = g_w1[tid & 511];
        #pragma unroll 8
        for (int r2 = 0; r2 < 64; r2++)
            b_s[r2 * PAD + tid] = fmaf(agrs[r2], wj, uj);
    }
    __syncthreads();

    // ======== 4 routing iterations (identical to R14) ========
    const uint4* bbase = (const uint4*)g_AtB + (wrp * 2) * 32 + lane;

    for (int it = 0; it < 4; it++) {
        float mx = -3.4e38f;
        #pragma unroll
        for (int j = 0; j < 16; j++) {
            float4 v = *(const float4*)(base + j * 32);
            mx = fmaxf(mx, fmaxf(fmaxf(v.x, v.y), fmaxf(v.z, v.w)));
        }
        #pragma unroll
        for (int o = 4; o > 0; o >>= 1) mx = fmaxf(mx, __shfl_xor_sync(0xffffffffu, mx, o));
        float m = mx;
        float s = 0.0f;
        #pragma unroll
        for (int j = 0; j < 16; j++) {
            float4 v = *(const float4*)(base + j * 32);
            s += __expf((v.x - m) * invT) + __expf((v.y - m) * invT)
               + __expf((v.z - m) * invT) + __expf((v.w - m) * invT);
        }
        #pragma unroll
        for (int o = 4; o > 0; o >>= 1) s += __shfl_xor_sync(0xffffffffu, s, o);
        float aS = agrs[r] / s;
        #pragma unroll
        for (int j = 0; j < 16; j++) {
            float4 v = *(const float4*)(base + j * 32);
            v.x = fmaf(aS, __expf((v.x - m) * invT), v.x);
            v.y = fmaf(aS, __expf((v.y - m) * invT), v.y);
            v.z = fmaf(aS, __expf((v.z - m) * invT), v.z);
            v.w = fmaf(aS, __expf((v.w - m) * invT), v.w);
            *(float4*)(base + j * 32) = v;
            *(uint2*)(bhrow + j * 16) = make_uint2(packhf(v.x, v.y), packhf(v.z, v.w));
        }
        __syncthreads();

        float acc[4][4][4];
        #pragma unroll
        for (int mt = 0; mt < 4; mt++)
            #pragma unroll
            for (int nt = 0; nt < 4; nt++)
                #pragma unroll
                for (int q = 0; q < 4; q++) acc[mt][nt][q] = 0.0f;

        uint4 B0 = bbase[0], B1 = bbase[32];
        #pragma unroll 4
        for (int gg = 0; gg < 32; gg++) {
            uint4 C0, C1;
            if (gg < 31) {
                const uint4* nb = bbase + (gg + 1) * 1024;
                C0 = nb[0]; C1 = nb[32];
            }
            const int kb = gg * 8 + (lane & 3);
            #pragma unroll
            for (int mt = 0; mt < 4; mt++) {
                int ra = (mt * 16 + (lane >> 2)) * BHS + kb;
                unsigned a0 = bh[ra];
                unsigned a1 = bh[ra + 8 * BHS];
                unsigned a2 = bh[ra + 4];
                unsigned a3 = bh[ra + 8 * BHS + 4];
                MMA_F16(acc[mt][0], a0, a1, a2, a3, B0.x, B0.y);
                MMA_F16(acc[mt][1], a0, a1, a2, a3, B0.z, B0.w);
                MMA_F16(acc[mt][2], a0, a1, a2, a3, B1.x, B1.y);
                MMA_F16(acc[mt][3], a0, a1, a2, a3, B1.z, B1.w);
            }
            B0 = C0; B1 = C1;
        }

        #pragma unroll
        for (int mt = 0; mt < 4; mt++) {
            int row = mt * 16 + (lane >> 2);
            #pragma unroll
            for (int nt = 0; nt < 4; nt++) {
                int col = wrp * 32 + nt * 8 + 2 * (lane & 3);
                float* p = b_s + row * PAD + col;
                p[0]           += acc[mt][nt][0];
                p[1]           += acc[mt][nt][1];
                p[8 * PAD]     += acc[mt][nt][2];
                p[8 * PAD + 1] += acc[mt][nt][3];
            }
        }
        __syncthreads();
    }

    // ======== theta = softmax(b/T) -> out ========
    {
        float mx = -3.4e38f;
        #pragma unroll
        for (int j = 0; j < 16; j++) {
            float4 v = *(const float4*)(base + j * 32);
            mx = fmaxf(mx, fmaxf(fmaxf(v.x, v.y), fmaxf(v.z, v.w)));
        }
        #pragma unroll
        for (int o = 4; o > 0; o >>= 1) mx = fmaxf(mx, __shfl_xor_sync(0xffffffffu, mx, o));
        float m = mx;
        float s = 0.0f;
        #pragma unroll
        for (int j = 0; j < 16; j++) {
            float4 v = *(const float4*)(base + j * 32);
            s += __expf((v.x - m) * invT) + __expf((v.y - m) * invT)
               + __expf((v.z - m) * invT) + __expf((v.w - m) * invT);
        }
        #pragma unroll
        for (int o = 4; o > 0; o >>= 1) s += __shfl_xor_sync(0xffffffffu, s, o);
        float iS = 1.0f / s;
        float* op = out + (size_t)(row0 + r) * KCAP + t8 * 4;
        #pragma unroll
        for (int j = 0; j < 16; j++) {
            float4 v = *(const float4*)(base + j * 32);
            float4 o;
            o.x = __expf((v.x - m) * invT) * iS;
            o.y = __expf((v.y - m) * invT) * iS;
            o.z = __expf((v.z - m) * invT) * iS;
            o.w = __expf((v.w - m) * invT) * iS;
            *(float4*)(op + j * 32) = o;
        }
    }
}

// ---------------- launcher ----------------
extern "C" void kernel_launch(void* const* d_in, const int* in_sizes, int n_in,
                              void* d_out, int out_size) {
    const float* x    = (const float*)d_in[0];
    const float* W    = (const float*)d_in[1];
    const float* A    = (const float*)d_in[2];
    const float* lT   = (const float*)d_in[3];
    const float* lc   = (const float*)d_in[4];
    const float* brun = (const float*)d_in[5];
    const void*  temp = d_in[6];
    const int B = in_sizes[0] / DDIM;   // 16384

    cudaFuncSetAttribute(k_main, cudaFuncAttributeMaxDynamicSharedMemorySize,
                         SMEM_MAIN_BYTES);

    k_scalars<<<1, 32>>>(lT, lc, temp);
    k_adiff<<<KCAP, 256>>>(A);
    k_prep<<<16, 256>>>(brun);
    k_convx<<<B / 16, 256>>>(x);
    k_convw<<<KCAP / 16, 256>>>(W);
    k_main<<<B / 64, 512, SMEM_MAIN_BYTES>>>((float*)d_out);
}